// round 9
// baseline (speedup 1.0000x reference)
#include <cuda_runtime.h>
#include <cuda_fp16.h>
#include <cstdint>

#define Nn   20000
#define Ee   320000
#define XDIM 128
#define Hh   256
#define LL   4
#define GG   128
#define CC   10
#define EPSF 1e-5f

#define KP2TOT ((XDIM + LL * Hh) / 2)   // 576 packed k-pair rows

// ---------------- scratch ----------------
__device__ float g_h [Nn * Hh];                 // enc output (conv0 A)
__device__ unsigned int g_th[Nn * Hh / 2];      // conv GEMM output, half2 packed
__device__ float g_t2[Nn * Hh];                 // post-agg fp32 (BN stats / next A / pool)
__device__ unsigned int g_wbh[KP2TOT * Hh];     // fp16-hi weights, packed k-pairs
__device__ unsigned int g_wbl[KP2TOT * Hh];     // fp16-lo residual
__device__ float g_dinv[Nn];
__device__ int   g_deg[Nn];
__device__ int   g_rowptr[Nn + 1];
__device__ int   g_cursor[Nn];
__device__ int   g_csrc[Ee];
__device__ float g_cw[Ee];
__device__ float g_colsum[Hh];
__device__ float g_colsq[Hh];
__device__ float g_scale[Hh];
__device__ float g_shift[Hh];
__device__ float g_gsum[GG * Hh];
__device__ int   g_gcnt[GG];
__device__ float g_m1[GG * Hh];
__device__ float g_m2[GG * Hh];

// ---------------- fp16 split helpers ----------------
__device__ __forceinline__ void split_h2(float a, float b,
                                         unsigned int& hi, unsigned int& lo) {
    __half ha = __float2half_rn(a), hb = __float2half_rn(b);
    float ra = a - __half2float(ha);
    float rb = b - __half2float(hb);
    __half2 h = __halves2half2(ha, hb);
    __half2 l = __halves2half2(__float2half_rn(ra), __float2half_rn(rb));
    hi = *reinterpret_cast<unsigned int*>(&h);
    lo = *reinterpret_cast<unsigned int*>(&l);
}

__device__ __forceinline__ void mma_f16(float4& d,
    unsigned int a0, unsigned int a1, unsigned int a2, unsigned int a3,
    unsigned int b0, unsigned int b1)
{
    asm volatile(
        "mma.sync.aligned.m16n8k16.row.col.f32.f16.f16.f32 "
        "{%0,%1,%2,%3}, {%4,%5,%6,%7}, {%8,%9}, {%0,%1,%2,%3};\n"
        : "+f"(d.x), "+f"(d.y), "+f"(d.z), "+f"(d.w)
        : "r"(a0), "r"(a1), "r"(a2), "r"(a3), "r"(b0), "r"(b1));
}

// ---------------- setup ----------------
__global__ void zero_k() {
    int i = blockIdx.x * blockDim.x + threadIdx.x;
    if (i < Nn)      g_deg[i]  = 0;
    if (i < GG * Hh) g_gsum[i] = 0.f;
    if (i < GG)      g_gcnt[i] = 0;
    if (i < Hh)      { g_colsum[i] = 0.f; g_colsq[i] = 0.f; }
}

// pre-split + pre-pack all weights into fp16 hi/lo, k-pair packed layout [kp][256]
__global__ void prep_k(const float* __restrict__ encW, const float* __restrict__ convW) {
    int i = blockIdx.x * blockDim.x + threadIdx.x;
    if (i >= KP2TOT * Hh) return;
    int kp = i >> 8;
    int n  = i & 255;
    int r0 = kp * 2, r1 = r0 + 1;
    float a = (r0 < XDIM) ? encW[r0 * Hh + n] : convW[(size_t)(r0 - XDIM) * Hh + n];
    float b = (r1 < XDIM) ? encW[r1 * Hh + n] : convW[(size_t)(r1 - XDIM) * Hh + n];
    unsigned int hi, lo;
    split_h2(a, b, hi, lo);
    g_wbh[i] = hi;
    g_wbl[i] = lo;
}

__global__ void degree_k(const int* __restrict__ dst, const int* __restrict__ batch) {
    int i = blockIdx.x * blockDim.x + threadIdx.x;
    if (i < Ee) atomicAdd(&g_deg[dst[i]], 1);
    if (i < Nn) atomicAdd(&g_gcnt[batch[i]], 1);
}

// scan (vectorized) + dinv
__global__ void scan_k() {
    __shared__ int wsum[32];
    const int CH = 20;
    int tid = threadIdx.x, lane = tid & 31, wid = tid >> 5;
    int base = tid * CH;
    int dv[CH];
    int s = 0;
    if (base < Nn) {
        const int4* dp = (const int4*)(g_deg + base);
#pragma unroll
        for (int q = 0; q < 5; q++) {
            int4 t = dp[q];
            dv[q * 4 + 0] = t.x; dv[q * 4 + 1] = t.y;
            dv[q * 4 + 2] = t.z; dv[q * 4 + 3] = t.w;
        }
#pragma unroll
        for (int c = 0; c < CH; c++) s += dv[c];
    }
    int inc = s;
#pragma unroll
    for (int o = 1; o < 32; o <<= 1) {
        int t = __shfl_up_sync(0xffffffffu, inc, o);
        if (lane >= o) inc += t;
    }
    if (lane == 31) wsum[wid] = inc;
    __syncthreads();
    if (wid == 0) {
        int v = wsum[lane];
        int iv = v;
#pragma unroll
        for (int o = 1; o < 32; o <<= 1) {
            int t = __shfl_up_sync(0xffffffffu, iv, o);
            if (lane >= o) iv += t;
        }
        wsum[lane] = iv - v;
    }
    __syncthreads();
    int off = wsum[wid] + (inc - s);
    if (base < Nn) {
        int p[CH];
        int run = off;
#pragma unroll
        for (int c = 0; c < CH; c++) { p[c] = run; run += dv[c]; }
        int4*   rp = (int4*)(g_rowptr + base);
        int4*   cp = (int4*)(g_cursor + base);
        float4* fp = (float4*)(g_dinv + base);
#pragma unroll
        for (int q = 0; q < 5; q++) {
            int4 t; t.x = p[q*4]; t.y = p[q*4+1]; t.z = p[q*4+2]; t.w = p[q*4+3];
            rp[q] = t; cp[q] = t;
            float4 f;
            f.x = rsqrtf((float)dv[q*4+0] + 1.f);
            f.y = rsqrtf((float)dv[q*4+1] + 1.f);
            f.z = rsqrtf((float)dv[q*4+2] + 1.f);
            f.w = rsqrtf((float)dv[q*4+3] + 1.f);
            fp[q] = f;
        }
    }
    if (base == Nn) g_rowptr[Nn] = off;
}

__global__ void place_k(const int* __restrict__ src, const int* __restrict__ dst) {
    int i = blockIdx.x * blockDim.x + threadIdx.x;
    if (i >= Ee) return;
    int s = src[i], d = dst[i];
    int pos = atomicAdd(&g_cursor[d], 1);
    g_csrc[pos] = s;
    g_cw[pos]   = g_dinv[s] * g_dinv[d];
}

// ---------------- split-FP16 tensor-core GEMM (R6 structure), double-buffered ----------------
#define BM 128
#define BN 64
#define BK 16
// mode 0: enc  (A=x,   +bias,              -> g_h fp32)
// mode 1: conv (A=g_h, raw,                -> g_th half2)
// mode 2: conv (A=relu(g_t2*scale+shift),  -> g_th half2)
__global__ __launch_bounds__(256) void gemm_k(const float* __restrict__ xin,
                                              const float* __restrict__ bias,
                                              int mode, int wofs2) {
    __shared__ unsigned int Ah[2][8][BM], Al[2][8][BM];
    __shared__ unsigned int Bh[2][8][BN], Bl[2][8][BN];

    const int K  = (mode == 0) ? XDIM : Hh;
    const int KT = K / BK;
    const float* A = (mode == 0) ? xin : (mode == 1 ? g_h : g_t2);

    const int tid  = threadIdx.x;
    const int lane = tid & 31, wid = tid >> 5;
    const int warp_m = wid & 3, warp_n = wid >> 2;
    const int rowBase = blockIdx.y * BM, colBase = blockIdx.x * BN;

    const int arow = tid >> 1;            // 0..127
    const int ak8  = (tid & 1) * 8;       // 0 or 8
    const int akp  = (tid & 1) * 4;       // kpair plane base
    const int bkp  = tid >> 5;            // 0..7
    const int bcol = lane * 2;            // 0..62
    const int q = lane >> 2, t = lane & 3, tsw = t << 3;

    const int gr = rowBase + arow;
    const float* aptr = A + (size_t)gr * K + ak8;
    const unsigned int* bhp = g_wbh + wofs2 + (size_t)bkp * Hh + colBase + bcol;
    const unsigned int* blp = g_wbl + wofs2 + (size_t)bkp * Hh + colBase + bcol;
    const int bstep = 8 * Hh;
    const int bcs = bcol ^ ((bkp & 3) << 3);

    float4 acc[2][4];
#pragma unroll
    for (int i = 0; i < 2; i++)
#pragma unroll
        for (int j = 0; j < 4; j++) acc[i][j] = make_float4(0.f, 0.f, 0.f, 0.f);

    float va[8];
    uint2 rbh, rbl;

    // ---- prologue: fetch tile 0 ----
    {
        float4 v0 = make_float4(0.f,0.f,0.f,0.f), v1 = v0;
        if (gr < Nn) { v0 = *(const float4*)aptr; v1 = *(const float4*)(aptr + 4); }
        va[0]=v0.x; va[1]=v0.y; va[2]=v0.z; va[3]=v0.w;
        va[4]=v1.x; va[5]=v1.y; va[6]=v1.z; va[7]=v1.w;
        if (mode == 2) {
            int kk = ak8;
#pragma unroll
            for (int c = 0; c < 8; c++)
                va[c] = fmaxf(va[c] * g_scale[kk + c] + g_shift[kk + c], 0.f);
        }
        rbh = *(const uint2*)bhp;
        rbl = *(const uint2*)blp;
    }
#pragma unroll
    for (int c2 = 0; c2 < 4; c2++) {
        unsigned int hi, lo;
        split_h2(va[2*c2], va[2*c2+1], hi, lo);
        int col = arow ^ (c2 << 3);
        Ah[0][akp + c2][col] = hi;
        Al[0][akp + c2][col] = lo;
    }
    *(uint2*)&Bh[0][bkp][bcs] = rbh;
    *(uint2*)&Bl[0][bkp][bcs] = rbl;
    __syncthreads();

    for (int kt = 0; kt < KT; kt++) {
        const int cur = kt & 1;
        const bool more = (kt + 1 < KT);
        if (more) {
            float4 v0 = make_float4(0.f,0.f,0.f,0.f), v1 = v0;
            if (gr < Nn) {
                const float* ap = aptr + (kt + 1) * BK;
                v0 = *(const float4*)ap; v1 = *(const float4*)(ap + 4);
            }
            va[0]=v0.x; va[1]=v0.y; va[2]=v0.z; va[3]=v0.w;
            va[4]=v1.x; va[5]=v1.y; va[6]=v1.z; va[7]=v1.w;
            if (mode == 2) {
                int kk = (kt + 1) * BK + ak8;
#pragma unroll
                for (int c = 0; c < 8; c++)
                    va[c] = fmaxf(va[c] * g_scale[kk + c] + g_shift[kk + c], 0.f);
            }
            rbh = *(const uint2*)(bhp + (size_t)(kt + 1) * bstep);
            rbl = *(const uint2*)(blp + (size_t)(kt + 1) * bstep);
        }
        // ---- compute on cur buffer ----
        unsigned int bh0[4], bh1[4], bl0[4], bl1[4];
#pragma unroll
        for (int j = 0; j < 4; j++) {
            int nb = (warp_n * 32 + j * 8 + q) ^ tsw;
            bh0[j] = Bh[cur][t][nb];     bh1[j] = Bh[cur][t + 4][nb];
            bl0[j] = Bl[cur][t][nb];     bl1[j] = Bl[cur][t + 4][nb];
        }
#pragma unroll
        for (int i = 0; i < 2; i++) {
            int r  = warp_m * 32 + i * 16 + q;
            int rs  = r ^ tsw;
            int rs8 = (r + 8) ^ tsw;
            unsigned int ah0 = Ah[cur][t][rs],     ah1 = Ah[cur][t][rs8];
            unsigned int ah2 = Ah[cur][t + 4][rs], ah3 = Ah[cur][t + 4][rs8];
            unsigned int al0 = Al[cur][t][rs],     al1 = Al[cur][t][rs8];
            unsigned int al2 = Al[cur][t + 4][rs], al3 = Al[cur][t + 4][rs8];
#pragma unroll
            for (int j = 0; j < 4; j++) {
                mma_f16(acc[i][j], ah0, ah1, ah2, ah3, bh0[j], bh1[j]);
                mma_f16(acc[i][j], ah0, ah1, ah2, ah3, bl0[j], bl1[j]);
                mma_f16(acc[i][j], al0, al1, al2, al3, bh0[j], bh1[j]);
            }
        }
        if (more) {
            const int nxt = cur ^ 1;
#pragma unroll
            for (int c2 = 0; c2 < 4; c2++) {
                unsigned int hi, lo;
                split_h2(va[2*c2], va[2*c2+1], hi, lo);
                int col = arow ^ (c2 << 3);
                Ah[nxt][akp + c2][col] = hi;
                Al[nxt][akp + c2][col] = lo;
            }
            *(uint2*)&Bh[nxt][bkp][bcs] = rbh;
            *(uint2*)&Bl[nxt][bkp][bcs] = rbl;
        }
        __syncthreads();
    }

    // ---- epilogue ----
#pragma unroll
    for (int i = 0; i < 2; i++) {
#pragma unroll
        for (int j = 0; j < 4; j++) {
            int r0 = rowBase + warp_m * 32 + i * 16 + q;
            int c  = colBase + warp_n * 32 + j * 8 + t * 2;
            if (mode == 0) {
                float bx = bias[c], by = bias[c + 1];
                if (r0 < Nn) {
                    g_h[(size_t)r0 * Hh + c]     = acc[i][j].x + bx;
                    g_h[(size_t)r0 * Hh + c + 1] = acc[i][j].y + by;
                }
                if (r0 + 8 < Nn) {
                    g_h[(size_t)(r0 + 8) * Hh + c]     = acc[i][j].z + bx;
                    g_h[(size_t)(r0 + 8) * Hh + c + 1] = acc[i][j].w + by;
                }
            } else {
                if (r0 < Nn) {
                    __half2 p = __floats2half2_rn(acc[i][j].x, acc[i][j].y);
                    g_th[((size_t)r0 * Hh + c) >> 1] = *(unsigned int*)&p;
                }
                if (r0 + 8 < Nn) {
                    __half2 p = __floats2half2_rn(acc[i][j].z, acc[i][j].w);
                    g_th[((size_t)(r0 + 8) * Hh + c) >> 1] = *(unsigned int*)&p;
                }
            }
        }
    }
}

// ---------------- aggregate (warp/node CSR gather over half2 t) + fused BN stats ----------------
__global__ __launch_bounds__(256) void agg_k(const float* __restrict__ convBi) {
    __shared__ float s_sum[Hh], s_sq[Hh];
    int tid = threadIdx.x, lane = tid & 31;
    s_sum[tid] = 0.f; s_sq[tid] = 0.f;
    __syncthreads();

    int w = blockIdx.x * 8 + (tid >> 5);   // grid = 2500 -> exact
    int beg = g_rowptr[w], end = g_rowptr[w + 1];
    float acc[8];
#pragma unroll
    for (int i = 0; i < 8; i++) acc[i] = 0.f;
    const uint4* TH = (const uint4*)g_th;  // row stride = 32 uint4 (256 halves)
    for (int e = beg; e < end; e++) {
        int   s  = g_csrc[e];
        float wt = g_cw[e];
        uint4 v = TH[s * 32 + lane];
        float2 f0 = __half22float2(*(const __half2*)&v.x);
        float2 f1 = __half22float2(*(const __half2*)&v.y);
        float2 f2 = __half22float2(*(const __half2*)&v.z);
        float2 f3 = __half22float2(*(const __half2*)&v.w);
        acc[0] += f0.x * wt; acc[1] += f0.y * wt;
        acc[2] += f1.x * wt; acc[3] += f1.y * wt;
        acc[4] += f2.x * wt; acc[5] += f2.y * wt;
        acc[6] += f3.x * wt; acc[7] += f3.y * wt;
    }
    float sn = g_dinv[w]; sn *= sn;
    {
        uint4 v = TH[w * 32 + lane];
        float2 f0 = __half22float2(*(const __half2*)&v.x);
        float2 f1 = __half22float2(*(const __half2*)&v.y);
        float2 f2 = __half22float2(*(const __half2*)&v.z);
        float2 f3 = __half22float2(*(const __half2*)&v.w);
        acc[0] += f0.x * sn; acc[1] += f0.y * sn;
        acc[2] += f1.x * sn; acc[3] += f1.y * sn;
        acc[4] += f2.x * sn; acc[5] += f2.y * sn;
        acc[6] += f3.x * sn; acc[7] += f3.y * sn;
    }
    const float4* B4 = (const float4*)convBi;
    float4 b0 = B4[lane * 2], b1 = B4[lane * 2 + 1];
    acc[0] += b0.x; acc[1] += b0.y; acc[2] += b0.z; acc[3] += b0.w;
    acc[4] += b1.x; acc[5] += b1.y; acc[6] += b1.z; acc[7] += b1.w;

    float4* O = (float4*)(g_t2 + (size_t)w * Hh + lane * 8);
    float4 o0, o1;
    o0.x = acc[0]; o0.y = acc[1]; o0.z = acc[2]; o0.w = acc[3];
    o1.x = acc[4]; o1.y = acc[5]; o1.z = acc[6]; o1.w = acc[7];
    O[0] = o0; O[1] = o1;

    int c0 = lane * 8;
#pragma unroll
    for (int i = 0; i < 8; i++) {
        atomicAdd(&s_sum[c0 + i], acc[i]);
        atomicAdd(&s_sq[c0 + i],  acc[i] * acc[i]);
    }
    __syncthreads();
    atomicAdd(&g_colsum[tid], s_sum[tid]);
    atomicAdd(&g_colsq[tid],  s_sq[tid]);
}

__global__ void bnprep_k(const float* __restrict__ gamma, const float* __restrict__ beta) {
    int j = threadIdx.x;
    const float invN = 1.f / (float)Nn;
    float m  = g_colsum[j] * invN;
    float v  = g_colsq[j] * invN - m * m;
    float rs = rsqrtf(v + EPSF);
    float sc = gamma[j] * rs;
    g_scale[j] = sc;
    g_shift[j] = beta[j] - m * sc;
    g_colsum[j] = 0.f;
    g_colsq[j]  = 0.f;
}

// ---------------- global mean pool with fused final BN+ReLU ----------------
__global__ void pool_k(const int* __restrict__ batch) {
    int j  = threadIdx.x;
    int r0 = blockIdx.x * 80;
    float sc = g_scale[j], sh = g_shift[j];
    int cur = -1;
    float acc = 0.f;
    for (int r = 0; r < 80; r++) {
        int n = r0 + r;
        if (n >= Nn) break;
        int b = batch[n];
        if (b != cur) {
            if (cur >= 0) atomicAdd(&g_gsum[cur * Hh + j], acc);
            cur = b; acc = 0.f;
        }
        acc += fmaxf(g_t2[(size_t)n * Hh + j] * sc + sh, 0.f);
    }
    if (cur >= 0) atomicAdd(&g_gsum[cur * Hh + j], acc);
}

// ---------------- MLP head ----------------
__global__ void mlp1_k(const float* __restrict__ W, const float* __restrict__ b) {
    __shared__ float s[Hh];
    int tid = threadIdx.x;
    int g   = blockIdx.x;
    float inv = 1.f / fmaxf((float)g_gcnt[g], 1.f);
    s[tid] = g_gsum[g * Hh + tid] * inv;
    __syncthreads();
    float sum = b[tid];
#pragma unroll 8
    for (int k = 0; k < Hh; k++) sum += s[k] * W[k * Hh + tid];
    g_m1[g * Hh + tid] = sum;
}

__global__ void mlp2_k(const float* __restrict__ gamma, const float* __restrict__ beta,
                       const float* __restrict__ W, const float* __restrict__ b) {
    __shared__ float s[Hh];
    int tid = threadIdx.x;
    int g   = blockIdx.x;
    float su = 0.f, q = 0.f;
    for (int r = 0; r < GG; r++) { float v = g_m1[r * Hh + tid]; su += v; q += v * v; }
    float m   = su * (1.f / GG);
    float var = q * (1.f / GG) - m * m;
    float sc  = gamma[tid] * rsqrtf(var + EPSF);
    float sh  = beta[tid] - m * sc;
    s[tid] = fmaxf(g_m1[g * Hh + tid] * sc + sh, 0.f);
    __syncthreads();
    float sum = b[tid];
#pragma unroll 8
    for (int k = 0; k < Hh; k++) sum += s[k] * W[k * Hh + tid];
    g_m2[g * Hh + tid] = sum;
}

__global__ void final_k(const float* __restrict__ gamma, const float* __restrict__ beta,
                        const float* __restrict__ W3, const float* __restrict__ b3,
                        float* __restrict__ out) {
    __shared__ float s[Hh];
    int tid = threadIdx.x;
    int g   = blockIdx.x;
    float su = 0.f, q = 0.f;
    for (int r = 0; r < GG; r++) { float v = g_m2[r * Hh + tid]; su += v; q += v * v; }
    float m   = su * (1.f / GG);
    float var = q * (1.f / GG) - m * m;
    float sc  = gamma[tid] * rsqrtf(var + EPSF);
    float sh  = beta[tid] - m * sc;
    s[tid] = g_m2[g * Hh + tid] * sc + sh;
    __syncthreads();
    if (tid < CC) {
        float sum = b3[tid];
        for (int k = 0; k < Hh; k++) sum += s[k] * W3[k * CC + tid];
        out[g * CC + tid] = sum;
    }
}

// ---------------- launch ----------------
extern "C" void kernel_launch(void* const* d_in, const int* in_sizes, int n_in,
                              void* d_out, int out_size) {
    const float* x     = (const float*)d_in[0];
    const int*   ei    = (const int*)  d_in[1];
    const int*   batch = (const int*)  d_in[2];
    const float* encW  = (const float*)d_in[3];
    const float* encB  = (const float*)d_in[4];
    const float* convW = (const float*)d_in[5];
    const float* convB = (const float*)d_in[6];
    const float* bnG   = (const float*)d_in[7];
    const float* bnB   = (const float*)d_in[8];
    const float* fcW1  = (const float*)d_in[9];
    const float* fcB1  = (const float*)d_in[10];
    const float* fcG1  = (const float*)d_in[11];
    const float* fcBe1 = (const float*)d_in[12];
    const float* fcW2  = (const float*)d_in[13];
    const float* fcB2  = (const float*)d_in[14];
    const float* fcG2  = (const float*)d_in[15];
    const float* fcBe2 = (const float*)d_in[16];
    const float* fcW3  = (const float*)d_in[17];
    const float* fcB3  = (const float*)d_in[18];
    const int* srcp = ei;
    const int* dstp = ei + Ee;
    float* out = (float*)d_out;

    dim3 gg(Hh / BN, (Nn + BM - 1) / BM);

    zero_k<<<(GG * Hh + 255) / 256, 256>>>();
    prep_k<<<(KP2TOT * Hh + 255) / 256, 256>>>(encW, convW);
    gemm_k<<<gg, 256>>>(x, encB, 0, 0);                          // enc -> g_h
    gemm_k<<<gg, 256>>>(nullptr, nullptr, 1, (XDIM/2) * Hh);     // conv0 [capture slot 4]

    degree_k<<<(Ee + 255) / 256, 256>>>(dstp, batch);
    scan_k  <<<1, 1024>>>();
    place_k <<<(Ee + 255) / 256, 256>>>(srcp, dstp);

    agg_k   <<<Nn / 8, 256>>>(convB);
    bnprep_k<<<1, 256>>>(bnG, bnB);
    for (int l = 1; l < LL; l++) {
        gemm_k  <<<gg, 256>>>(nullptr, nullptr, 2, (XDIM/2 + l * Hh/2) * Hh);
        agg_k   <<<Nn / 8, 256>>>(convB + l * Hh);
        bnprep_k<<<1, 256>>>(bnG + l * Hh, bnB + l * Hh);
    }

    pool_k <<<250, 256>>>(batch);
    mlp1_k <<<GG, 256>>>(fcW1, fcB1);
    mlp2_k <<<GG, 256>>>(fcG1, fcBe1, fcW2, fcB2);
    final_k<<<GG, 256>>>(fcG2, fcBe2, fcW3, fcB3, out);
}